// round 9
// baseline (speedup 1.0000x reference)
#include <cuda_runtime.h>
#include <cuda_bf16.h>

// Soft-DTW (gamma=0.1), N=M=4096, squared-Euclidean cost, out = |R[N-1,M-1]|.
//
// R9: 128 blocks x 32 threads (ONE WARP per block) — fully warp-synchronous.
// Thread (b,lane) owns row i = 32b + lane; at block-local step s computes
// cell (i, j = s - lane).
//   u = R[i-1,j]:
//     - lanes 1..31: shfl.up of neighbor's previous-step q (no smem, no bar)
//     - lane 0 (b>0): boundary row streamed from block b-1 through global
//       memory, gated by the proven release/acquire progress counter:
//         writer (lane 31): buffers 8 cols in regs, flushes per half-group as
//           8x st.global.cg + ONE st.release.gpu (off the per-step path)
//         feeder (lane 0): 16-deep register FIFO, loads each half-group 8
//           steps ahead; early-issued acquire poll hides poll latency.
//   ZERO __syncthreads in the whole kernel (only one __syncwarp after
//   staging y into smem). 128 blocks <= 148 SMs -> all co-resident.
//   All values scaled q = R/(gamma*ln2): softmin via ex2/lg2.approx.ftz with
//   arguments clamped >= -150 (ftz-identical). Proven at rel_err 4e-5.

#define NN 4096
#define TPB 32
#define NBLK (NN / TPB)          // 128
#define NSTEPS 4128              // >= NN + TPB - 1 = 4127, multiple of 16

// Boundary rows between consecutive blocks + progress counters.
__device__ float g_bnd[(NBLK - 1) * NN];
__device__ int   g_prog[NBLK];

__device__ __forceinline__ float ex2f_(float a) {
    float r; asm("ex2.approx.ftz.f32 %0, %1;" : "=f"(r) : "f"(a)); return r;
}
__device__ __forceinline__ float lg2f_(float a) {
    float r; asm("lg2.approx.ftz.f32 %0, %1;" : "=f"(r) : "f"(a)); return r;
}
__device__ __forceinline__ float ldcgf_(const float* p) {
    float r; asm volatile("ld.global.cg.f32 %0, [%1];" : "=f"(r) : "l"(p)); return r;
}
__device__ __forceinline__ int ldacq_(const int* p) {
    int r; asm volatile("ld.acquire.gpu.global.s32 %0, [%1];" : "=r"(r) : "l"(p)); return r;
}
__device__ __forceinline__ void strel_(int* p, int v) {
    asm volatile("st.release.gpu.global.s32 [%0], %1;" :: "l"(p), "r"(v) : "memory");
}
__device__ __forceinline__ void stcgf_(float* p, float v) {
    asm volatile("st.global.cg.f32 [%0], %1;" :: "l"(p), "f"(v) : "memory");
}

__global__ void sdtw_reset() {
    if (threadIdx.x < NBLK) g_prog[threadIdx.x] = 0;
}

__global__ __launch_bounds__(TPB, 1)
void sdtw_main(const float* __restrict__ x, const float* __restrict__ y,
               float* __restrict__ out) {
    __shared__ float ysh[NN];            // targets, staged once (16 KB)

    const float KS   = 14.426950408889634f;    // 1/(gamma*ln2), gamma=0.1
    const float IKS  = 0.069314718055994531f;  // gamma*ln2
    const float BIGQ = 1.0e8f;                 // "infinity" in q units

    const int lane = threadIdx.x;              // one warp per block
    const int b    = blockIdx.x;
    const int row  = b * TPB + lane;

    for (int i = lane; i < NN; i += TPB) ysh[i] = y[i];
    const float xi = x[row];

    const float* bnd_in   = g_bnd + (b > 0 ? (b - 1) * NN : 0);
    float*       bnd_out  = g_bnd + (b < NBLK - 1 ? b * NN : 0);
    const int*   prog_in  = &g_prog[b > 0 ? b - 1 : 0];
    int*         prog_out = &g_prog[b < NBLK - 1 ? b : NBLK - 1];
    const bool feeder = (lane == 0) && (b > 0);
    const bool writer = (lane == TPB - 1) && (b < NBLK - 1);

    // Feeder register FIFO: pf[k] holds boundary column for step sb+k.
    float pf[16];
    #pragma unroll
    for (int k = 0; k < 16; ++k) pf[k] = 0.0f;
    int avail = 0, early = 0;
    if (feeder) {
        while ((avail = ldacq_(prog_in)) < 8) {}
        #pragma unroll
        for (int k = 0; k < 8; ++k) pf[k] = ldcgf_(bnd_in + k);
        early = avail;
    }

    // Writer register buffer: 8 boundary values per half-group.
    float wbuf[8];
    #pragma unroll
    for (int k = 0; k < 8; ++k) wbuf[k] = 0.0f;

    __syncwarp();

    float q = 0.0f;      // my q at previous column ('left')
    float uprev = 0.0f;  // u used at previous column ('diag')

#define STEP(S, PFK, K)                                                       \
    {                                                                         \
        float u = __shfl_up_sync(0xFFFFFFFFu, q, 1);                          \
        if (lane == 0)                                                        \
            u = (b == 0) ? BIGQ : (((S) < NN) ? (PFK) : 0.0f);                \
        const int j = (S) - lane;                                             \
        if (j >= 0 && j < NN) {                                               \
            float l  = (j == 0) ? BIGQ : q;                                   \
            float g  = (j == 0) ? ((row == 0) ? 0.0f : BIGQ) : uprev;         \
            float uu = (row == 0) ? BIGQ : u;                                 \
            float dy = xi - ysh[j];                                           \
            float dk = dy * dy * KS;                                          \
            float m  = fminf(uu, fminf(l, g));                                \
            float e  = ex2f_(fmaxf(m - uu, -150.0f))                          \
                     + ex2f_(fmaxf(m - l,  -150.0f))                          \
                     + ex2f_(fmaxf(m - g,  -150.0f));                         \
            q     = dk + (m - lg2f_(e));                                      \
            uprev = uu;                                                       \
        }                                                                     \
        wbuf[K] = q;                                                          \
    }

    // Writer flush: 8 plain .cg stores + ONE release, between half-groups.
#define WFLUSH(SB)                                                            \
    if (writer) {                                                             \
        const int base = (SB) - (TPB - 1);                                    \
        _Pragma("unroll")                                                     \
        for (int k = 0; k < 8; ++k) {                                         \
            const int jj = base + k;                                          \
            if (jj >= 0 && jj < NN) stcgf_(bnd_out + jj, wbuf[k]);            \
        }                                                                     \
        int c = base + 8; if (c > NN) c = NN;                                 \
        if (c > 0) strel_(prog_out, c);                                       \
    }

    #pragma unroll 1
    for (int sb = 0; sb < NSTEPS; sb += 16) {
        if (feeder) {
            int lim = sb + 16; if (lim > NN) lim = NN;
            if (avail < lim) {
                if (early > avail) avail = early;
                while (avail < lim) avail = ldacq_(prog_in);
            }
            #pragma unroll
            for (int k = 8; k < 16; ++k) {
                const int c = sb + k;
                if (c < NN) pf[k] = ldcgf_(bnd_in + c);
            }
            early = ldacq_(prog_in);   // early poll for next half-group
        }
        #pragma unroll
        for (int k = 0; k < 8; ++k) STEP(sb + k, pf[k], k)
        WFLUSH(sb)

        if (feeder) {
            int lim = sb + 24; if (lim > NN) lim = NN;
            if (avail < lim) {
                if (early > avail) avail = early;
                while (avail < lim) avail = ldacq_(prog_in);
            }
            #pragma unroll
            for (int k = 0; k < 8; ++k) {
                const int c = sb + 16 + k;
                if (c < NN) pf[k] = ldcgf_(bnd_in + c);
            }
            early = ldacq_(prog_in);
        }
        #pragma unroll
        for (int k = 8; k < 16; ++k) STEP(sb + k, pf[k], k - 8)
        WFLUSH(sb + 8)
    }
#undef STEP
#undef WFLUSH

    if (lane == TPB - 1 && b == NBLK - 1)
        out[0] = fabsf(q * IKS);
}

extern "C" void kernel_launch(void* const* d_in, const int* in_sizes, int n_in,
                              void* d_out, int out_size) {
    const float* xin = (const float*)d_in[0];   // inputs  -> rows
    const float* yin = (const float*)d_in[1];   // targets -> cols
    float* outp = (float*)d_out;
    sdtw_reset<<<1, NBLK>>>();
    sdtw_main<<<NBLK, TPB>>>(xin, yin, outp);
}

// round 10
// speedup vs baseline: 3.3831x; 3.3831x over previous
#include <cuda_runtime.h>
#include <cuda_bf16.h>

// Soft-DTW (gamma=0.1), N=M=4096, squared-Euclidean cost, out = |R[N-1,M-1]|.
//
// R10 = R8 (proven 1532us) + phase-split main loop:
//   prologue  s in [0,128)    : guarded STEP (j<0, j==0 edges)      — 8 groups
//   steady    s in [128,4096) : BRANCHLESS STEP (all lanes valid)   — 248 groups
//   epilogue  s in [4096,4224): guarded STEP (j>=NN edges)          — 8 groups
// Steady step replaces 3-4 divergent regions (~150 cyc of BSSY/BSYNC per
// step) with an all-lane broadcast LDS + SELs. Feeder/writer cadence and all
// indices are byte-identical to R8.
//
// Structure (unchanged): 32 blocks x 128 threads, thread-per-row wavefront.
//   u = R[i-1,j]: lanes 1..31 shfl.up; warps via wslot parity smem + bar/step;
//   blocks via global boundary rows gated by a release/acquire progress
//   counter (writer batches 8 cols: 8x st.cg + ONE st.release per half-group;
//   feeder: 16-deep register FIFO + early acquire poll).
//   All values scaled q = R/(gamma*ln2); softmin via ex2/lg2.approx.ftz,
//   args clamped >= -150. Proven at rel_err 3.96e-5.

#define NN 4096
#define TPB 128
#define NBLK (NN / TPB)          // 32
#define NSTEPS 4224              // >= NN + TPB - 1 = 4223, multiple of 16

__device__ float g_bnd[(NBLK - 1) * NN];
__device__ int   g_prog[NBLK];

__device__ __forceinline__ float ex2f_(float a) {
    float r; asm("ex2.approx.ftz.f32 %0, %1;" : "=f"(r) : "f"(a)); return r;
}
__device__ __forceinline__ float lg2f_(float a) {
    float r; asm("lg2.approx.ftz.f32 %0, %1;" : "=f"(r) : "f"(a)); return r;
}
__device__ __forceinline__ float ldcgf_(const float* p) {
    float r; asm volatile("ld.global.cg.f32 %0, [%1];" : "=f"(r) : "l"(p)); return r;
}
__device__ __forceinline__ int ldacq_(const int* p) {
    int r; asm volatile("ld.acquire.gpu.global.s32 %0, [%1];" : "=r"(r) : "l"(p)); return r;
}
__device__ __forceinline__ void strel_(int* p, int v) {
    asm volatile("st.release.gpu.global.s32 [%0], %1;" :: "l"(p), "r"(v) : "memory");
}
__device__ __forceinline__ void stcgf_(float* p, float v) {
    asm volatile("st.global.cg.f32 [%0], %1;" :: "l"(p), "f"(v) : "memory");
}

__global__ void sdtw_reset() {
    if (threadIdx.x < NBLK) g_prog[threadIdx.x] = 0;
}

__global__ __launch_bounds__(TPB, 1)
void sdtw_main(const float* __restrict__ x, const float* __restrict__ y,
               float* __restrict__ out) {
    __shared__ float ysh[NN];            // targets, staged once (16 KB)
    __shared__ float wslot[2][TPB / 32]; // [step parity][warp] handoff

    const float KS   = 14.426950408889634f;    // 1/(gamma*ln2), gamma=0.1
    const float IKS  = 0.069314718055994531f;  // gamma*ln2
    const float BIGQ = 1.0e8f;                 // "infinity" in q units

    const int tid  = threadIdx.x;
    const int b    = blockIdx.x;
    const int w    = tid >> 5;
    const int lane = tid & 31;
    const int row  = b * TPB + tid;
    const int wm1  = (w > 0) ? (w - 1) : 0;    // clamped for all-lane LDS
    const bool row0 = (row == 0);

    for (int i = tid; i < NN; i += TPB) ysh[i] = y[i];
    const float xi = x[row];

    const float* bnd_in   = g_bnd + (b > 0 ? (b - 1) * NN : 0);
    float*       bnd_out  = g_bnd + (b < NBLK - 1 ? b * NN : 0);
    const int*   prog_in  = &g_prog[b > 0 ? b - 1 : 0];
    int*         prog_out = &g_prog[b < NBLK - 1 ? b : NBLK - 1];
    const bool feeder = (tid == 0) && (b > 0);
    const bool writer = (tid == TPB - 1) && (b < NBLK - 1);

    // Feeder register FIFO: pf[k] holds boundary column for step sb+k.
    float pf[16];
    #pragma unroll
    for (int k = 0; k < 16; ++k) pf[k] = 0.0f;
    int avail = 0, early = 0;
    if (feeder) {
        while ((avail = ldacq_(prog_in)) < 8) {}
        #pragma unroll
        for (int k = 0; k < 8; ++k) pf[k] = ldcgf_(bnd_in + k);
        early = avail;
    }

    // Writer register buffer: 8 boundary values per half-group.
    float wbuf[8];
    #pragma unroll
    for (int k = 0; k < 8; ++k) wbuf[k] = 0.0f;

    __syncthreads();

    float q = 0.0f;      // my q at previous column ('left')
    float uprev = 0.0f;  // u used at previous column ('diag')

// Guarded step (prologue/epilogue) — byte-identical to R8's proven STEP.
#define STEPG(S, PFK, K)                                                      \
    {                                                                         \
        float u = __shfl_up_sync(0xFFFFFFFFu, q, 1);                          \
        if (lane == 0) {                                                      \
            if (w > 0)          u = wslot[((S) + 1) & 1][w - 1];              \
            else if (b == 0)    u = BIGQ;                                     \
            else if ((S) < NN)  u = (PFK);                                    \
        }                                                                     \
        const int j = (S) - tid;                                              \
        if (j >= 0 && j < NN) {                                               \
            float l  = (j == 0) ? BIGQ : q;                                   \
            float g  = (j == 0) ? ((row == 0) ? 0.0f : BIGQ) : uprev;         \
            float uu = (row == 0) ? BIGQ : u;                                 \
            float dy = xi - ysh[j];                                           \
            float dk = dy * dy * KS;                                          \
            float m  = fminf(uu, fminf(l, g));                                \
            float e  = ex2f_(fmaxf(m - uu, -150.0f))                          \
                     + ex2f_(fmaxf(m - l,  -150.0f))                          \
                     + ex2f_(fmaxf(m - g,  -150.0f));                         \
            q     = dk + (m - lg2f_(e));                                      \
            uprev = uu;                                                       \
        }                                                                     \
        if (lane == 31) wslot[(S) & 1][w] = q;                                \
        wbuf[K] = q;                                                          \
        __syncthreads();                                                      \
    }

// Branchless steady step: valid for S in [TPB, NN) where every lane has
// j = S - tid in [1, NN) (no j<0, no j==0, no j>=NN). Same operands,
// same arithmetic, control flow via SELs.
#define STEPS(S, PFK, K)                                                      \
    {                                                                         \
        float u  = __shfl_up_sync(0xFFFFFFFFu, q, 1);                         \
        float wv = wslot[((S) + 1) & 1][wm1];     /* all-lane broadcast */    \
        float pfb = (b == 0) ? BIGQ : (PFK);                                  \
        u = (lane == 0) ? ((w > 0) ? wv : pfb) : u;                           \
        float uu = row0 ? BIGQ : u;                                           \
        float dy = xi - ysh[(S) - tid];                                       \
        float dk = dy * dy * KS;                                              \
        float m  = fminf(uu, fminf(q, uprev));                                \
        float e  = ex2f_(fmaxf(m - uu,    -150.0f))                           \
                 + ex2f_(fmaxf(m - q,     -150.0f))                           \
                 + ex2f_(fmaxf(m - uprev, -150.0f));                          \
        q     = dk + (m - lg2f_(e));                                          \
        uprev = uu;                                                           \
        if (lane == 31) wslot[(S) & 1][w] = q;                                \
        wbuf[K] = q;                                                          \
        __syncthreads();                                                      \
    }

// Writer flush: 8 plain .cg stores + ONE release, between half-groups.
#define WFLUSH(SB)                                                            \
    if (writer) {                                                             \
        const int base = (SB) - (TPB - 1);                                    \
        _Pragma("unroll")                                                     \
        for (int k = 0; k < 8; ++k) {                                         \
            const int jj = base + k;                                          \
            if (jj >= 0 && jj < NN) stcgf_(bnd_out + jj, wbuf[k]);            \
        }                                                                     \
        int c = base + 8; if (c > NN) c = NN;                                 \
        if (c > 0) strel_(prog_out, c);                                       \
    }

// One 16-step group with the R8 feeder/writer cadence; STEPM picks the body.
#define GROUP16(SBX, STEPM)                                                   \
    {                                                                         \
        const int sb_ = (SBX);                                                \
        if (feeder) {                                                         \
            int lim = sb_ + 16; if (lim > NN) lim = NN;                       \
            if (avail < lim) {                                                \
                if (early > avail) avail = early;                             \
                while (avail < lim) avail = ldacq_(prog_in);                  \
            }                                                                 \
            _Pragma("unroll")                                                 \
            for (int k = 8; k < 16; ++k) {                                    \
                const int c = sb_ + k;                                        \
                if (c < NN) pf[k] = ldcgf_(bnd_in + c);                       \
            }                                                                 \
            early = ldacq_(prog_in);                                          \
        }                                                                     \
        _Pragma("unroll")                                                     \
        for (int k = 0; k < 8; ++k) STEPM(sb_ + k, pf[k], k)                  \
        WFLUSH(sb_)                                                           \
        if (feeder) {                                                         \
            int lim = sb_ + 24; if (lim > NN) lim = NN;                       \
            if (avail < lim) {                                                \
                if (early > avail) avail = early;                             \
                while (avail < lim) avail = ldacq_(prog_in);                  \
            }                                                                 \
            _Pragma("unroll")                                                 \
            for (int k = 0; k < 8; ++k) {                                     \
                const int c = sb_ + 16 + k;                                   \
                if (c < NN) pf[k] = ldcgf_(bnd_in + c);                       \
            }                                                                 \
            early = ldacq_(prog_in);                                          \
        }                                                                     \
        _Pragma("unroll")                                                     \
        for (int k = 8; k < 16; ++k) STEPM(sb_ + k, pf[k], k - 8)             \
        WFLUSH(sb_ + 8)                                                       \
    }

    // Prologue: s in [0, 128) — j<0 and j==0 edges live here.
    #pragma unroll 1
    for (int sb = 0; sb < TPB; sb += 16) GROUP16(sb, STEPG)

    // Steady: s in [128, 4096) — every lane valid, branchless body.
    #pragma unroll 1
    for (int sb = TPB; sb < NN; sb += 16) GROUP16(sb, STEPS)

    // Epilogue: s in [4096, 4224) — j>=NN edges live here.
    #pragma unroll 1
    for (int sb = NN; sb < NSTEPS; sb += 16) GROUP16(sb, STEPG)

#undef STEPG
#undef STEPS
#undef WFLUSH
#undef GROUP16

    if (tid == TPB - 1 && b == NBLK - 1)
        out[0] = fabsf(q * IKS);
}

extern "C" void kernel_launch(void* const* d_in, const int* in_sizes, int n_in,
                              void* d_out, int out_size) {
    const float* xin = (const float*)d_in[0];   // inputs  -> rows
    const float* yin = (const float*)d_in[1];   // targets -> cols
    float* outp = (float*)d_out;
    sdtw_reset<<<1, NBLK>>>();
    sdtw_main<<<NBLK, TPB>>>(xin, yin, outp);
}

// round 13
// speedup vs baseline: 3.4848x; 1.0301x over previous
#include <cuda_runtime.h>
#include <cuda_bf16.h>

// Soft-DTW (gamma=0.1), N=M=4096, squared-Euclidean cost, out = |R[N-1,M-1]|.
//
// R13 = R10 (proven 1278us skeleton) with C=2 columns per thread per step.
// 32 blocks x 128 threads; thread (b,t) owns row i = 128b + t; at macro-step
// s it computes column PAIR p = s - t (cols 2p, 2p+1). Per-step overhead
// (barrier, shfl, wslot, feeder/writer) amortizes over 2 cells and the
// cross-block skew lag halves in columns.
//   u = (R[i-1,2p], R[i-1,2p+1]) = neighbor's previous-step pair:
//     - lanes 1..31: two shfl.up (independent, latencies overlap)
//     - warps: wslot[2][4] float2 parity smem + per-step __syncthreads (R8)
//     - blocks: float2 boundary rows + release/acquire PAIR counter (R8):
//       writer batches 8 pairs in regs, flushes 8x st.cg.v2 + ONE
//       st.release.gpu per 8-step half-group; feeder keeps a 16-deep float2
//       register FIFO with group-level waits + early acquire poll.
//   In-pair: col 2p   uses up=u0, left=q1(prev pair), diag=u1(prev pair);
//            col 2p+1 uses up=u1, left=q0(just computed), diag=u0.
//   Cell operand ordering identical to R10 -> same rel_err 3.96e-5.
//   Phase-split: guarded prologue/epilogue, branchless steady.
//   All values scaled q = R/(gamma*ln2); softmin via ex2/lg2.approx.ftz,
//   args clamped >= -150.

#define NN 4096
#define TPB 128
#define NBLK (NN / TPB)          // 32
#define NPAIR (NN / 2)           // 2048 column pairs
#define NMSTEPS 2176             // >= NPAIR + TPB - 1 = 2175, multiple of 16

__device__ float2 g_bnd[(NBLK - 1) * NPAIR];
__device__ int    g_prog[NBLK];

__device__ __forceinline__ float ex2f_(float a) {
    float r; asm("ex2.approx.ftz.f32 %0, %1;" : "=f"(r) : "f"(a)); return r;
}
__device__ __forceinline__ float lg2f_(float a) {
    float r; asm("lg2.approx.ftz.f32 %0, %1;" : "=f"(r) : "f"(a)); return r;
}
__device__ __forceinline__ float2 ldcgf2_(const float2* p) {
    float2 v;
    asm volatile("ld.global.cg.v2.f32 {%0,%1}, [%2];"
                 : "=f"(v.x), "=f"(v.y) : "l"(p));
    return v;
}
__device__ __forceinline__ void stcgf2_(float2* p, float2 v) {
    asm volatile("st.global.cg.v2.f32 [%0], {%1,%2};"
                 :: "l"(p), "f"(v.x), "f"(v.y) : "memory");
}
__device__ __forceinline__ int ldacq_(const int* p) {
    int r; asm volatile("ld.acquire.gpu.global.s32 %0, [%1];" : "=r"(r) : "l"(p)); return r;
}
__device__ __forceinline__ void strel_(int* p, int v) {
    asm volatile("st.release.gpu.global.s32 [%0], %1;" :: "l"(p), "r"(v) : "memory");
}

__global__ void sdtw_reset() {
    if (threadIdx.x < NBLK) g_prog[threadIdx.x] = 0;
}

__global__ __launch_bounds__(TPB, 1)
void sdtw_main(const float* __restrict__ x, const float* __restrict__ y,
               float* __restrict__ out) {
    __shared__ float2 ysh2[NPAIR];        // targets as pairs (16 KB)
    __shared__ float2 wslot[2][TPB / 32]; // [step parity][warp] pair handoff

    const float KS   = 14.426950408889634f;    // 1/(gamma*ln2), gamma=0.1
    const float IKS  = 0.069314718055994531f;  // gamma*ln2
    const float BIGQ = 1.0e8f;                 // "infinity" in q units

    const int tid  = threadIdx.x;
    const int b    = blockIdx.x;
    const int w    = tid >> 5;
    const int lane = tid & 31;
    const int row  = b * TPB + tid;
    const int wm1  = (w > 0) ? (w - 1) : 0;
    const bool row0 = (row == 0);

    const float2* y2 = reinterpret_cast<const float2*>(y);
    for (int i = tid; i < NPAIR; i += TPB) ysh2[i] = y2[i];
    const float xi = x[row];

    const float2* bnd_in   = g_bnd + (b > 0 ? (b - 1) * NPAIR : 0);
    float2*       bnd_out  = g_bnd + (b < NBLK - 1 ? b * NPAIR : 0);
    const int*    prog_in  = &g_prog[b > 0 ? b - 1 : 0];
    int*          prog_out = &g_prog[b < NBLK - 1 ? b : NBLK - 1];
    const bool feeder = (tid == 0) && (b > 0);
    const bool writer = (tid == TPB - 1) && (b < NBLK - 1);

    // Feeder register FIFO: pf[k] holds boundary PAIR for macro-step sb+k.
    float2 pf[16];
    #pragma unroll
    for (int k = 0; k < 16; ++k) pf[k] = make_float2(0.0f, 0.0f);
    int avail = 0, early = 0;
    if (feeder) {
        while ((avail = ldacq_(prog_in)) < 8) {}
        #pragma unroll
        for (int k = 0; k < 8; ++k) pf[k] = ldcgf2_(bnd_in + k);
        early = avail;
    }

    // Writer register buffer: 8 boundary pairs per half-group.
    float2 wbuf[8];
    #pragma unroll
    for (int k = 0; k < 8; ++k) wbuf[k] = make_float2(0.0f, 0.0f);

    __syncthreads();

    float q0 = 0.0f, q1 = 0.0f;  // my pair values from the previous step
    float qp1 = 0.0f;            // q1 of previous pair  = R[i, 2p-1]
    float up1 = 0.0f;            // uu1 of previous pair = R[i-1, 2p-1]

// Guarded step (prologue/epilogue): handles p<0, p==0, p>=NPAIR edges.
#define STEPG(S, PFK, K)                                                      \
    {                                                                         \
        float u0 = __shfl_up_sync(0xFFFFFFFFu, q0, 1);                        \
        float u1 = __shfl_up_sync(0xFFFFFFFFu, q1, 1);                        \
        if (lane == 0) {                                                      \
            if (w > 0) {                                                      \
                float2 wv = wslot[((S) + 1) & 1][w - 1];                      \
                u0 = wv.x; u1 = wv.y;                                         \
            } else if (b == 0) {                                              \
                u0 = BIGQ; u1 = BIGQ;                                         \
            } else if ((S) < NPAIR) {                                         \
                u0 = (PFK).x; u1 = (PFK).y;                                   \
            }                                                                 \
        }                                                                     \
        const int p = (S) - tid;                                              \
        if (p >= 0 && p < NPAIR) {                                            \
            float uu0 = row0 ? BIGQ : u0;                                     \
            float uu1 = row0 ? BIGQ : u1;                                     \
            float l0  = (p == 0) ? BIGQ : qp1;                                \
            float g0  = (p == 0) ? (row0 ? 0.0f : BIGQ) : up1;                \
            float2 yv = ysh2[p];                                              \
            float dy0 = xi - yv.x;                                            \
            float m0  = fminf(uu0, fminf(l0, g0));                            \
            float e0  = ex2f_(fmaxf(m0 - uu0, -150.0f))                       \
                      + ex2f_(fmaxf(m0 - l0,  -150.0f))                       \
                      + ex2f_(fmaxf(m0 - g0,  -150.0f));                      \
            q0 = dy0 * dy0 * KS + (m0 - lg2f_(e0));                           \
            float dy1 = xi - yv.y;                                            \
            float m1  = fminf(uu1, fminf(q0, uu0));                           \
            float e1  = ex2f_(fmaxf(m1 - uu1, -150.0f))                       \
                      + ex2f_(fmaxf(m1 - q0,  -150.0f))                       \
                      + ex2f_(fmaxf(m1 - uu0, -150.0f));                      \
            q1 = dy1 * dy1 * KS + (m1 - lg2f_(e1));                           \
            qp1 = q1; up1 = uu1;                                              \
        }                                                                     \
        if (lane == 31) wslot[(S) & 1][w] = make_float2(q0, q1);              \
        wbuf[K] = make_float2(q0, q1);                                        \
        __syncthreads();                                                      \
    }

// Branchless steady step: S in [TPB, NPAIR) -> every lane has p in [1,NPAIR).
#define STEPS_(S, PFK, K)                                                     \
    {                                                                         \
        float u0 = __shfl_up_sync(0xFFFFFFFFu, q0, 1);                        \
        float u1 = __shfl_up_sync(0xFFFFFFFFu, q1, 1);                        \
        float2 wv = wslot[((S) + 1) & 1][wm1];    /* all-lane broadcast */    \
        float pb0 = (b == 0) ? BIGQ : (PFK).x;                                \
        float pb1 = (b == 0) ? BIGQ : (PFK).y;                                \
        u0 = (lane == 0) ? ((w > 0) ? wv.x : pb0) : u0;                       \
        u1 = (lane == 0) ? ((w > 0) ? wv.y : pb1) : u1;                       \
        float uu0 = row0 ? BIGQ : u0;                                         \
        float uu1 = row0 ? BIGQ : u1;                                         \
        float2 yv = ysh2[(S) - tid];                                          \
        float dy0 = xi - yv.x;                                                \
        float m0  = fminf(uu0, fminf(qp1, up1));                              \
        float e0  = ex2f_(fmaxf(m0 - uu0, -150.0f))                           \
                  + ex2f_(fmaxf(m0 - qp1, -150.0f))                           \
                  + ex2f_(fmaxf(m0 - up1, -150.0f));                          \
        q0 = dy0 * dy0 * KS + (m0 - lg2f_(e0));                               \
        float dy1 = xi - yv.y;                                                \
        float m1  = fminf(uu1, fminf(q0, uu0));                               \
        float e1  = ex2f_(fmaxf(m1 - uu1, -150.0f))                           \
                  + ex2f_(fmaxf(m1 - q0,  -150.0f))                           \
                  + ex2f_(fmaxf(m1 - uu0, -150.0f));                          \
        q1 = dy1 * dy1 * KS + (m1 - lg2f_(e1));                               \
        qp1 = q1; up1 = uu1;                                                  \
        if (lane == 31) wslot[(S) & 1][w] = make_float2(q0, q1);              \
        wbuf[K] = make_float2(q0, q1);                                        \
        __syncthreads();                                                      \
    }

// Writer flush: 8 plain .cg.v2 stores + ONE release, between half-groups.
#define WFLUSH(SB)                                                            \
    if (writer) {                                                             \
        const int base = (SB) - (TPB - 1);                                    \
        _Pragma("unroll")                                                     \
        for (int k = 0; k < 8; ++k) {                                         \
            const int jj = base + k;                                          \
            if (jj >= 0 && jj < NPAIR) stcgf2_(bnd_out + jj, wbuf[k]);        \
        }                                                                     \
        int c = base + 8; if (c > NPAIR) c = NPAIR;                           \
        if (c > 0) strel_(prog_out, c);                                       \
    }

// One 16-step group with the proven R8/R10 feeder/writer cadence.
#define GROUP16(SBX, STEPM)                                                   \
    {                                                                         \
        const int sb_ = (SBX);                                                \
        if (feeder) {                                                         \
            int lim = sb_ + 16; if (lim > NPAIR) lim = NPAIR;                 \
            if (avail < lim) {                                                \
                if (early > avail) avail = early;                             \
                while (avail < lim) avail = ldacq_(prog_in);                  \
            }                                                                 \
            _Pragma("unroll")                                                 \
            for (int k = 8; k < 16; ++k) {                                    \
                const int c = sb_ + k;                                        \
                if (c < NPAIR) pf[k] = ldcgf2_(bnd_in + c);                   \
            }                                                                 \
            early = ldacq_(prog_in);                                          \
        }                                                                     \
        _Pragma("unroll")                                                     \
        for (int k = 0; k < 8; ++k) STEPM(sb_ + k, pf[k], k)                  \
        WFLUSH(sb_)                                                           \
        if (feeder) {                                                         \
            int lim = sb_ + 24; if (lim > NPAIR) lim = NPAIR;                 \
            if (avail < lim) {                                                \
                if (early > avail) avail = early;                             \
                while (avail < lim) avail = ldacq_(prog_in);                  \
            }                                                                 \
            _Pragma("unroll")                                                 \
            for (int k = 0; k < 8; ++k) {                                     \
                const int c = sb_ + 16 + k;                                   \
                if (c < NPAIR) pf[k] = ldcgf2_(bnd_in + c);                   \
            }                                                                 \
            early = ldacq_(prog_in);                                          \
        }                                                                     \
        _Pragma("unroll")                                                     \
        for (int k = 8; k < 16; ++k) STEPM(sb_ + k, pf[k], k - 8)             \
        WFLUSH(sb_ + 8)                                                       \
    }

    // Prologue: s in [0, 128) — p<0 and p==0 edges.
    #pragma unroll 1
    for (int sb = 0; sb < TPB; sb += 16) GROUP16(sb, STEPG)

    // Steady: s in [128, 2048) — branchless.
    #pragma unroll 1
    for (int sb = TPB; sb < NPAIR; sb += 16) GROUP16(sb, STEPS_)

    // Epilogue: s in [2048, 2176) — p>=NPAIR edges; feeder idle.
    #pragma unroll 1
    for (int sb = NPAIR; sb < NMSTEPS; sb += 16) GROUP16(sb, STEPG)

#undef STEPG
#undef STEPS_
#undef WFLUSH
#undef GROUP16

    if (tid == TPB - 1 && b == NBLK - 1)
        out[0] = fabsf(q1 * IKS);   // q1 = R[4095, 4095]
}

extern "C" void kernel_launch(void* const* d_in, const int* in_sizes, int n_in,
                              void* d_out, int out_size) {
    const float* xin = (const float*)d_in[0];   // inputs  -> rows
    const float* yin = (const float*)d_in[1];   // targets -> cols
    float* outp = (float*)d_out;
    sdtw_reset<<<1, NBLK>>>();
    sdtw_main<<<NBLK, TPB>>>(xin, yin, outp);
}

// round 14
// speedup vs baseline: 4.2025x; 1.2059x over previous
#include <cuda_runtime.h>
#include <cuda_bf16.h>

// Soft-DTW (gamma=0.1), N=M=4096, squared-Euclidean cost, out = |R[N-1,M-1]|.
//
// R14: 2x2 CELL TILE per thread. 32 blocks x 64 threads; thread t owns rows
// {rowA, rowB} = {128b + 2t, 128b + 2t + 1}; at macro-step s it computes the
// 2x2 tile (rows A,B) x (cols 2p, 2p+1), p = s - t.
//   Makespan slots ~ NN/R + NN/C = 2048 + 2048 (vs 4096+2048 at R=1).
//   Handoff payload UNCHANGED from proven R13: the thread-above's BOTTOM-row
//   pair (qb0,qb1): lanes via 2x shfl.up; warps via float2 parity wslot +
//   per-step bar; blocks via float2 boundary rows + release/acquire pair
//   counter (writer: 8 pairs batched, 8x st.cg.v2 + ONE st.release per
//   8-step half-group; feeder: 16-deep float2 register FIFO, group waits,
//   early acquire poll).
//   Tile deps: A0(up=u0,left=qa1-,diag=dga-), A1(up=u1,left=A0,diag=u0),
//              B0(up=A0,left=qb1-,diag=old qa1-), B1(up=A1,left=B0,diag=A0).
//   Carried: qa1, dga(=prev uu1), qb0, qb1.
//   Per-cell arithmetic identical to R13 -> same rel_err 3.96e-5.
//   All values scaled q = R/(gamma*ln2); softmin via ex2/lg2.approx.ftz,
//   args clamped >= -150.

#define NN 4096
#define TPB 64
#define NBLK 32                  // block covers TPB*2 = 128 rows
#define NPAIR (NN / 2)           // 2048 column pairs
#define NMSTEPS 2112             // >= NPAIR + TPB - 1 = 2111, multiple of 16

__device__ float2 g_bnd[(NBLK - 1) * NPAIR];
__device__ int    g_prog[NBLK];

__device__ __forceinline__ float ex2f_(float a) {
    float r; asm("ex2.approx.ftz.f32 %0, %1;" : "=f"(r) : "f"(a)); return r;
}
__device__ __forceinline__ float lg2f_(float a) {
    float r; asm("lg2.approx.ftz.f32 %0, %1;" : "=f"(r) : "f"(a)); return r;
}
__device__ __forceinline__ float2 ldcgf2_(const float2* p) {
    float2 v;
    asm volatile("ld.global.cg.v2.f32 {%0,%1}, [%2];"
                 : "=f"(v.x), "=f"(v.y) : "l"(p));
    return v;
}
__device__ __forceinline__ void stcgf2_(float2* p, float2 v) {
    asm volatile("st.global.cg.v2.f32 [%0], {%1,%2};"
                 :: "l"(p), "f"(v.x), "f"(v.y) : "memory");
}
__device__ __forceinline__ int ldacq_(const int* p) {
    int r; asm volatile("ld.acquire.gpu.global.s32 %0, [%1];" : "=r"(r) : "l"(p)); return r;
}
__device__ __forceinline__ void strel_(int* p, int v) {
    asm volatile("st.release.gpu.global.s32 [%0], %1;" :: "l"(p), "r"(v) : "memory");
}

__global__ void sdtw_reset() {
    if (threadIdx.x < NBLK) g_prog[threadIdx.x] = 0;
}

// One cell: returns q = d*KS + softmin(up, left, diag), scaled units.
__device__ __forceinline__ float cellq_(float dy, float up, float l, float g,
                                        float KS) {
    float m = fminf(up, fminf(l, g));
    float e = ex2f_(fmaxf(m - up, -150.0f))
            + ex2f_(fmaxf(m - l,  -150.0f))
            + ex2f_(fmaxf(m - g,  -150.0f));
    return dy * dy * KS + (m - lg2f_(e));
}

__global__ __launch_bounds__(TPB, 1)
void sdtw_main(const float* __restrict__ x, const float* __restrict__ y,
               float* __restrict__ out) {
    __shared__ float2 ysh2[NPAIR];        // targets as pairs (16 KB)
    __shared__ float2 wslot[2][TPB / 32]; // [step parity][warp] pair handoff

    const float KS   = 14.426950408889634f;    // 1/(gamma*ln2), gamma=0.1
    const float IKS  = 0.069314718055994531f;  // gamma*ln2
    const float BIGQ = 1.0e8f;                 // "infinity" in q units

    const int tid  = threadIdx.x;
    const int b    = blockIdx.x;
    const int w    = tid >> 5;
    const int lane = tid & 31;
    const int rowA = b * (TPB * 2) + 2 * tid;
    const int wm1  = (w > 0) ? (w - 1) : 0;
    const bool rowA0 = (rowA == 0);            // only b==0, tid==0

    const float2* y2 = reinterpret_cast<const float2*>(y);
    for (int i = tid; i < NPAIR; i += TPB) ysh2[i] = y2[i];
    const float xi0 = x[rowA];
    const float xi1 = x[rowA + 1];

    const float2* bnd_in   = g_bnd + (b > 0 ? (b - 1) * NPAIR : 0);
    float2*       bnd_out  = g_bnd + (b < NBLK - 1 ? b * NPAIR : 0);
    const int*    prog_in  = &g_prog[b > 0 ? b - 1 : 0];
    int*          prog_out = &g_prog[b < NBLK - 1 ? b : NBLK - 1];
    const bool feeder = (tid == 0) && (b > 0);
    const bool writer = (tid == TPB - 1) && (b < NBLK - 1);

    // Feeder register FIFO: pf[k] holds boundary PAIR for macro-step sb+k.
    float2 pf[16];
    #pragma unroll
    for (int k = 0; k < 16; ++k) pf[k] = make_float2(0.0f, 0.0f);
    int avail = 0, early = 0;
    if (feeder) {
        while ((avail = ldacq_(prog_in)) < 8) {}
        #pragma unroll
        for (int k = 0; k < 8; ++k) pf[k] = ldcgf2_(bnd_in + k);
        early = avail;
    }

    // Writer register buffer: 8 boundary pairs per half-group.
    float2 wbuf[8];
    #pragma unroll
    for (int k = 0; k < 8; ++k) wbuf[k] = make_float2(0.0f, 0.0f);

    __syncthreads();

    // Carried state (values for column pair p-1 after each step):
    float qa1 = 0.0f;   // R[rowA, 2p-1]  (A-left, B-diag source)
    float dga = 0.0f;   // R[rowA-1, 2p-1] (A-diag; prev step's uu1)
    float qb0 = 0.0f;   // R[rowB, 2p-2]? -> after step: R[rowB,2p], handoff
    float qb1 = 0.0f;   // R[rowB, 2p-1]  (B-left; handoff)

// Guarded step (prologue/epilogue): handles p<0, p==0, p>=NPAIR edges.
#define STEPG(S, PFK, K)                                                      \
    {                                                                         \
        float u0 = __shfl_up_sync(0xFFFFFFFFu, qb0, 1);                       \
        float u1 = __shfl_up_sync(0xFFFFFFFFu, qb1, 1);                       \
        if (lane == 0) {                                                      \
            if (w > 0) {                                                      \
                float2 wv = wslot[((S) + 1) & 1][w - 1];                      \
                u0 = wv.x; u1 = wv.y;                                         \
            } else if (b == 0) {                                              \
                u0 = BIGQ; u1 = BIGQ;                                         \
            } else if ((S) < NPAIR) {                                         \
                u0 = (PFK).x; u1 = (PFK).y;                                   \
            }                                                                 \
        }                                                                     \
        const int p = (S) - tid;                                              \
        if (p >= 0 && p < NPAIR) {                                            \
            float uu0 = rowA0 ? BIGQ : u0;                                    \
            float uu1 = rowA0 ? BIGQ : u1;                                    \
            float la  = (p == 0) ? BIGQ : qa1;                                \
            float ga  = (p == 0) ? (rowA0 ? 0.0f : BIGQ) : dga;               \
            float lb  = (p == 0) ? BIGQ : qb1;                                \
            float gb  = (p == 0) ? BIGQ : qa1;   /* old qa1 = R[rowA,2p-1] */ \
            float2 yv = ysh2[p];                                              \
            float na0 = cellq_(xi0 - yv.x, uu0, la,  ga,  KS);                \
            float na1 = cellq_(xi0 - yv.y, uu1, na0, uu0, KS);                \
            float nb0 = cellq_(xi1 - yv.x, na0, lb,  gb,  KS);                \
            float nb1 = cellq_(xi1 - yv.y, na1, nb0, na0, KS);                \
            qa1 = na1; dga = uu1; qb0 = nb0; qb1 = nb1;                       \
        }                                                                     \
        if (lane == 31) wslot[(S) & 1][w] = make_float2(qb0, qb1);            \
        wbuf[K] = make_float2(qb0, qb1);                                      \
        __syncthreads();                                                      \
    }

// Branchless steady step: S in [TPB, NPAIR) -> every lane has p in [1,NPAIR).
#define STEPS_(S, PFK, K)                                                     \
    {                                                                         \
        float u0 = __shfl_up_sync(0xFFFFFFFFu, qb0, 1);                       \
        float u1 = __shfl_up_sync(0xFFFFFFFFu, qb1, 1);                       \
        float2 wv = wslot[((S) + 1) & 1][wm1];    /* all-lane broadcast */    \
        float pb0 = (b == 0) ? BIGQ : (PFK).x;                                \
        float pb1 = (b == 0) ? BIGQ : (PFK).y;                                \
        u0 = (lane == 0) ? ((w > 0) ? wv.x : pb0) : u0;                       \
        u1 = (lane == 0) ? ((w > 0) ? wv.y : pb1) : u1;                       \
        float uu0 = rowA0 ? BIGQ : u0;                                        \
        float uu1 = rowA0 ? BIGQ : u1;                                        \
        float2 yv = ysh2[(S) - tid];                                          \
        float na0 = cellq_(xi0 - yv.x, uu0, qa1, dga, KS);                    \
        float na1 = cellq_(xi0 - yv.y, uu1, na0, uu0, KS);                    \
        float nb0 = cellq_(xi1 - yv.x, na0, qb1, qa1, KS);                    \
        float nb1 = cellq_(xi1 - yv.y, na1, nb0, na0, KS);                    \
        qa1 = na1; dga = uu1; qb0 = nb0; qb1 = nb1;                           \
        if (lane == 31) wslot[(S) & 1][w] = make_float2(qb0, qb1);            \
        wbuf[K] = make_float2(qb0, qb1);                                      \
        __syncthreads();                                                      \
    }

// Writer flush: 8 plain .cg.v2 stores + ONE release, between half-groups.
#define WFLUSH(SB)                                                            \
    if (writer) {                                                             \
        const int base = (SB) - (TPB - 1);                                    \
        _Pragma("unroll")                                                     \
        for (int k = 0; k < 8; ++k) {                                         \
            const int jj = base + k;                                          \
            if (jj >= 0 && jj < NPAIR) stcgf2_(bnd_out + jj, wbuf[k]);        \
        }                                                                     \
        int c = base + 8; if (c > NPAIR) c = NPAIR;                           \
        if (c > 0) strel_(prog_out, c);                                       \
    }

// One 16-step group with the proven R8/R10 feeder/writer cadence.
#define GROUP16(SBX, STEPM)                                                   \
    {                                                                         \
        const int sb_ = (SBX);                                                \
        if (feeder) {                                                         \
            int lim = sb_ + 16; if (lim > NPAIR) lim = NPAIR;                 \
            if (avail < lim) {                                                \
                if (early > avail) avail = early;                             \
                while (avail < lim) avail = ldacq_(prog_in);                  \
            }                                                                 \
            _Pragma("unroll")                                                 \
            for (int k = 8; k < 16; ++k) {                                    \
                const int c = sb_ + k;                                        \
                if (c < NPAIR) pf[k] = ldcgf2_(bnd_in + c);                   \
            }                                                                 \
            early = ldacq_(prog_in);                                          \
        }                                                                     \
        _Pragma("unroll")                                                     \
        for (int k = 0; k < 8; ++k) STEPM(sb_ + k, pf[k], k)                  \
        WFLUSH(sb_)                                                           \
        if (feeder) {                                                         \
            int lim = sb_ + 24; if (lim > NPAIR) lim = NPAIR;                 \
            if (avail < lim) {                                                \
                if (early > avail) avail = early;                             \
                while (avail < lim) avail = ldacq_(prog_in);                  \
            }                                                                 \
            _Pragma("unroll")                                                 \
            for (int k = 0; k < 8; ++k) {                                     \
                const int c = sb_ + 16 + k;                                   \
                if (c < NPAIR) pf[k] = ldcgf2_(bnd_in + c);                   \
            }                                                                 \
            early = ldacq_(prog_in);                                          \
        }                                                                     \
        _Pragma("unroll")                                                     \
        for (int k = 8; k < 16; ++k) STEPM(sb_ + k, pf[k], k - 8)             \
        WFLUSH(sb_ + 8)                                                       \
    }

    // Prologue: s in [0, 64) — p<0 and p==0 edges.
    #pragma unroll 1
    for (int sb = 0; sb < TPB; sb += 16) GROUP16(sb, STEPG)

    // Steady: s in [64, 2048) — branchless.
    #pragma unroll 1
    for (int sb = TPB; sb < NPAIR; sb += 16) GROUP16(sb, STEPS_)

    // Epilogue: s in [2048, 2112) — p>=NPAIR edges; feeder idle.
    #pragma unroll 1
    for (int sb = NPAIR; sb < NMSTEPS; sb += 16) GROUP16(sb, STEPG)

#undef STEPG
#undef STEPS_
#undef WFLUSH
#undef GROUP16

    if (tid == TPB - 1 && b == NBLK - 1)
        out[0] = fabsf(qb1 * IKS);   // qb1 = R[4095, 4095]
}

extern "C" void kernel_launch(void* const* d_in, const int* in_sizes, int n_in,
                              void* d_out, int out_size) {
    const float* xin = (const float*)d_in[0];   // inputs  -> rows
    const float* yin = (const float*)d_in[1];   // targets -> cols
    float* outp = (float*)d_out;
    sdtw_reset<<<1, NBLK>>>();
    sdtw_main<<<NBLK, TPB>>>(xin, yin, outp);
}